// round 1
// baseline (speedup 1.0000x reference)
#include <cuda_runtime.h>
#include <cstdint>

#define NNODES 50000
#define NEDGES 800000
#define EPSF 1e-7f

// ---------------- static device scratch (no allocations allowed) ----------------
__device__ __align__(16) float g_u0 [NNODES*128];   // log_map(x), col0 = 0
__device__ __align__(16) float g_acc[NNODES*128];   // xt + segment_sum
__device__ __align__(16) float g_v  [NNODES*384];   // GEMM output (mx tail, col0 = 0)
__device__ __align__(16) float g_bufA[NNODES*384];  // ping
__device__ __align__(16) float g_bufB[NNODES*384];  // pong
__device__ __align__(16) float g_Wp0[128*128];
__device__ __align__(16) float g_Wp1[256*128];
__device__ __align__(16) float g_Wp2[384*256];
__device__ float g_bp0[128];
__device__ float g_bp1[256];
__device__ float g_bp2[384];
__device__ float g_sums[384];

// ---------------- helpers ----------------
__device__ __forceinline__ float warpSum(float v){
#pragma unroll
    for (int o = 16; o > 0; o >>= 1) v += __shfl_xor_sync(0xffffffffu, v, o);
    return v;
}

// arcosh with the reference's clamp: x = max(x, 1+EPS); log(x + sqrt(x*x-1))
__device__ __forceinline__ float arcosh_cl(float x){
    x = fmaxf(x, 1.0f + EPSF);
    return logf(x + sqrtf(x * x - 1.0f));
}

// ---------------- weight padding: Wp[m][k] = W[m-1][k-1] (row0/col0 = 0) ----------------
template<int MPAD, int KPAD>
__global__ void prep_kernel(const float* __restrict__ W, const float* __restrict__ b,
                            float* __restrict__ Wp, float* __restrict__ bp){
    int idx = blockIdx.x * blockDim.x + threadIdx.x;
    if (idx < MPAD * KPAD){
        int m = idx / KPAD, k = idx % KPAD;
        Wp[idx] = (m >= 1 && k >= 1) ? W[(m - 1) * (KPAD - 1) + (k - 1)] : 0.0f;
    }
    if (idx < MPAD){
        bp[idx] = (idx >= 1) ? b[idx - 1] : 0.0f;
    }
}

// ---------------- log_map_zero(x) -> u0, and acc = u0 (GIN: (1+eps)*xt, eps=0) ----------------
__global__ void lmap0_kernel(const float* __restrict__ x){
    int warp = (blockIdx.x * blockDim.x + threadIdx.x) >> 5;
    if (warp >= NNODES) return;
    int lane = threadIdx.x & 31;
    float4 a = ((const float4*)x)[(size_t)warp * 32 + lane];
    float y0 = __shfl_sync(0xffffffffu, a.x, 0);
    float s = a.x*a.x + a.y*a.y + a.z*a.z + a.w*a.w;
    if (lane == 0) s = a.y*a.y + a.z*a.z + a.w*a.w;   // exclude leading coord
    float S = warpSum(s);
    float dist = arcosh_cl(y0 + EPSF);
    float g = dist / sqrtf(S + EPSF);
    float4 u;
    u.x = (lane == 0) ? 0.0f : g * a.x;
    u.y = g * a.y; u.z = g * a.z; u.w = g * a.w;
    ((float4*)g_u0 )[(size_t)warp * 32 + lane] = u;
    ((float4*)g_acc)[(size_t)warp * 32 + lane] = u;
}

// ---------------- segment_sum: acc[dst] += u0[src], one warp per edge ----------------
__global__ void scatter_kernel(const int* __restrict__ ei){
    int warp = (blockIdx.x * blockDim.x + threadIdx.x) >> 5;
    if (warp >= NEDGES) return;
    int lane = threadIdx.x & 31;
    int src = ei[warp];
    int dst = ei[NEDGES + warp];
    float4 v = ((const float4*)g_u0)[(size_t)src * 32 + lane];
    float* addr = g_acc + (size_t)dst * 128 + lane * 4;
    asm volatile("red.global.add.v4.f32 [%0], {%1,%2,%3,%4};"
                 :: "l"(addr), "f"(v.x), "f"(v.y), "f"(v.z), "f"(v.w) : "memory");
}

// ---------------- log_map(exp_map(acc)) -> bufA (GEMM input for layer 0) ----------------
__global__ void manpre_kernel(){
    int warp = (blockIdx.x * blockDim.x + threadIdx.x) >> 5;
    if (warp >= NNODES) return;
    int lane = threadIdx.x & 31;
    float4 a = ((const float4*)g_acc)[(size_t)warp * 32 + lane];  // col0 = 0
    float s = a.x*a.x + a.y*a.y + a.z*a.z + a.w*a.w;
    float S = warpSum(s);
    float n = sqrtf(fmaxf(S + EPSF, 1e-6f));
    float f = sinhf(fminf(n, 50.0f)) / n;
    float fS = f * f * S;
    float first = sqrtf(1.0f + fS);
    float dist = arcosh_cl(first + EPSF);
    float g = dist / sqrtf(fS + EPSF) * f;
    float4 u; u.x = g*a.x; u.y = g*a.y; u.z = g*a.z; u.w = g*a.w;
    ((float4*)g_bufA)[(size_t)warp * 32 + lane] = u;
}

// ---------------- per-row chain after GEMM: exp -> log -> relu -> exp -> log ----------------
// Input: v row (mx tail, col0 = 0). Output: u_next = log_map(lorentz_act(lorentz_linear)).tail
template<int MP>
__global__ void rowpost_kernel(const float* __restrict__ V, float* __restrict__ U){
    int warp = (blockIdx.x * blockDim.x + threadIdx.x) >> 5;
    if (warp >= NNODES) return;
    int lane = threadIdx.x & 31;
    constexpr int PL = MP / 128;  // float4 per lane
    const float4* vr = (const float4*)(V + (size_t)warp * MP);
    float4 a[PL];
    float s = 0.0f;
#pragma unroll
    for (int i = 0; i < PL; i++){
        a[i] = vr[i * 32 + lane];
        s += a[i].x*a[i].x + a[i].y*a[i].y + a[i].z*a[i].z + a[i].w*a[i].w;
    }
    float S = warpSum(s);
    // exp_map (lorentz_linear); cond (all-zero) collapses to the same numbers downstream
    float n = sqrtf(fmaxf(S + EPSF, 1e-6f));
    float f = sinhf(fminf(n, 50.0f)) / n;
    float fS = f * f * S;
    float first = sqrtf(1.0f + fS);
    // log_map then relu
    float dist = arcosh_cl(first + EPSF);
    float g1 = dist / sqrtf(fS + EPSF) * f;
    float s2 = 0.0f;
#pragma unroll
    for (int i = 0; i < PL; i++){
        a[i].x = fmaxf(g1 * a[i].x, 0.0f);
        a[i].y = fmaxf(g1 * a[i].y, 0.0f);
        a[i].z = fmaxf(g1 * a[i].z, 0.0f);
        a[i].w = fmaxf(g1 * a[i].w, 0.0f);
        s2 += a[i].x*a[i].x + a[i].y*a[i].y + a[i].z*a[i].z + a[i].w*a[i].w;
    }
    float S2 = warpSum(s2);
    // exp_map (lorentz_act) then log_map (next layer / final ht)
    float n2 = sqrtf(fmaxf(S2 + EPSF, 1e-6f));
    float f2 = sinhf(fminf(n2, 50.0f)) / n2;
    float f2S = f2 * f2 * S2;
    float first2 = sqrtf(1.0f + f2S);
    float dist2 = arcosh_cl(first2 + EPSF);
    float g2 = dist2 / sqrtf(f2S + EPSF) * f2;
    float4* ur = (float4*)(U + (size_t)warp * MP);
#pragma unroll
    for (int i = 0; i < PL; i++){
        float4 o; o.x = g2*a[i].x; o.y = g2*a[i].y; o.z = g2*a[i].z; o.w = g2*a[i].w;
        ur[i * 32 + lane] = o;
    }
}

// ---------------- fp32 SIMT GEMM: C[n][m] = A[n][:] . B[m][:] + bias[m] ----------------
// A: [NNODES x K] row-major, B: [M x K] row-major (both K-contiguous, "NT")
template<int K, int M>
__global__ void gemm_kernel(const float* __restrict__ A, const float* __restrict__ B,
                            const float* __restrict__ bias, float* __restrict__ C){
    __shared__ float As[16][64];
    __shared__ float Bs[16][64];
    int tid = threadIdx.x;
    int brow = blockIdx.y * 64;
    int bcol = blockIdx.x * 64;
    int tr = (tid >> 4) << 2;
    int tc = (tid & 15) << 2;
    int lr = tid >> 2;
    int lk = (tid & 3) << 2;
    float acc[4][4] = {};
    const float* Arow = A + (size_t)(brow + lr) * K + lk;
    const float* Brow = B + (size_t)(bcol + lr) * K + lk;
    bool avalid = (brow + lr) < NNODES;
#pragma unroll 2
    for (int k0 = 0; k0 < K; k0 += 16){
        float4 av = avalid ? *(const float4*)(Arow + k0) : make_float4(0,0,0,0);
        float4 bv = *(const float4*)(Brow + k0);
        As[lk+0][lr] = av.x; As[lk+1][lr] = av.y; As[lk+2][lr] = av.z; As[lk+3][lr] = av.w;
        Bs[lk+0][lr] = bv.x; Bs[lk+1][lr] = bv.y; Bs[lk+2][lr] = bv.z; Bs[lk+3][lr] = bv.w;
        __syncthreads();
#pragma unroll
        for (int k = 0; k < 16; k++){
            float4 a4 = *(const float4*)&As[k][tr];
            float4 b4 = *(const float4*)&Bs[k][tc];
            acc[0][0] += a4.x*b4.x; acc[0][1] += a4.x*b4.y; acc[0][2] += a4.x*b4.z; acc[0][3] += a4.x*b4.w;
            acc[1][0] += a4.y*b4.x; acc[1][1] += a4.y*b4.y; acc[1][2] += a4.y*b4.z; acc[1][3] += a4.y*b4.w;
            acc[2][0] += a4.z*b4.x; acc[2][1] += a4.z*b4.y; acc[2][2] += a4.z*b4.z; acc[2][3] += a4.z*b4.w;
            acc[3][0] += a4.w*b4.x; acc[3][1] += a4.w*b4.y; acc[3][2] += a4.w*b4.z; acc[3][3] += a4.w*b4.w;
        }
        __syncthreads();
    }
    float4 bb = *(const float4*)(bias + bcol + tc);
#pragma unroll
    for (int i = 0; i < 4; i++){
        int gr = brow + tr + i;
        if (gr < NNODES){
            float4 o;
            o.x = acc[i][0] + bb.x; o.y = acc[i][1] + bb.y;
            o.z = acc[i][2] + bb.z; o.w = acc[i][3] + bb.w;
            *(float4*)(C + (size_t)gr * M + bcol + tc) = o;
        }
    }
}

// ---------------- mean over nodes ----------------
__global__ void zero384_kernel(){ g_sums[threadIdx.x] = 0.0f; }

__global__ void mean_kernel(const float* __restrict__ U){
    int t = threadIdx.x;              // 384
    int start = blockIdx.x * 250;
    int end = start + 250;
    float s = 0.0f;
    for (int nn = start; nn < end; nn++) s += U[(size_t)nn * 384 + t];
    atomicAdd(&g_sums[t], s);
}

// ---------------- final classifier head (tiny) ----------------
__global__ void classify_kernel(const float* __restrict__ Wc, const float* __restrict__ bc,
                                float* __restrict__ out){
    __shared__ float sh_hm[384];
    __shared__ float sh_warp[16];
    __shared__ float sh_mx[10];
    __shared__ float sh_factor;
    int t = threadIdx.x, lane = t & 31, wid = t >> 5;   // 512 threads
    float v = 0.0f;
    if (t < 384) v = g_sums[t] * (1.0f / (float)NNODES);
    if (t == 0) v = 0.0f;                    // hm[0] = 0
    if (t < 384) sh_hm[t] = v;
    float s = warpSum(v * v);
    if (lane == 0) sh_warp[wid] = s;
    __syncthreads();
    if (t == 0){
        float S = 0.0f;
        for (int i = 0; i < 16; i++) S += sh_warp[i];
        float nrm = sqrtf(S + EPSF);
        float dist = arcosh_cl(0.0f + EPSF);  // y0 = hm[0] = 0
        sh_factor = dist / nrm;
    }
    __syncthreads();
    float factor = sh_factor;
    // mx[m] = (factor*hm_tail) . Wc[m-1][:] + bc[m-1]
    if (wid < 9){
        float d = 0.0f;
        for (int j = lane; j < 383; j += 32) d += sh_hm[j + 1] * factor * Wc[wid * 383 + j];
        d = warpSum(d);
        if (lane == 0) sh_mx[wid + 1] = d + bc[wid];
    }
    if (t == 0) sh_mx[0] = 0.0f;
    __syncthreads();
    if (t == 0){
        float mx[10];
#pragma unroll
        for (int i = 0; i < 10; i++) mx[i] = sh_mx[i];
        float S = 0.0f;
        for (int i = 1; i < 10; i++) S += mx[i] * mx[i];
        float n = sqrtf(fmaxf(S + EPSF, 1e-6f));
        float f = sinhf(fminf(n, 50.0f)) / n;
        float fS = f * f * S;
        float hc[10];
        bool cond = (S == 0.0f);   // all(mx == 0)
        if (cond){
            for (int i = 0; i < 10; i++) hc[i] = 0.0f;
        } else {
            hc[0] = sqrtf(1.0f + fS);
            for (int i = 1; i < 10; i++) hc[i] = f * mx[i];
        }
        for (int i = 0; i < 10; i++) out[i] = hc[i];
        // prob = lorentz_act(h_classify, softmax)
        float x0c = fmaxf(hc[0] + EPSF, 1.0f + EPSF);
        float dd = logf(x0c + sqrtf(x0c * x0c - 1.0f));
        float tn = 0.0f;
        for (int i = 1; i < 10; i++) tn += hc[i] * hc[i];
        float nr = sqrtf(tn + EPSF);
        float gf = dd / nr;
        float lt[10]; lt[0] = 0.0f;
        for (int i = 1; i < 10; i++) lt[i] = gf * hc[i];
        float mmax = lt[0];
        for (int i = 1; i < 10; i++) mmax = fmaxf(mmax, lt[i]);
        float e[10], se = 0.0f;
        for (int i = 0; i < 10; i++){ e[i] = expf(lt[i] - mmax); se += e[i]; }
        float p[10];
        for (int i = 0; i < 10; i++) p[i] = e[i] / se;
        p[0] = 0.0f;                              // set AFTER softmax (matches reference)
        float S3 = 0.0f;
        for (int i = 1; i < 10; i++) S3 += p[i] * p[i];
        float n3 = sqrtf(fmaxf(S3 + EPSF, 1e-6f));
        float f3 = sinhf(fminf(n3, 50.0f)) / n3;
        float f3S = f3 * f3 * S3;
        out[10] = sqrtf(1.0f + f3S);
        for (int i = 1; i < 10; i++) out[10 + i] = f3 * p[i];
    }
}

// ---------------- launch ----------------
extern "C" void kernel_launch(void* const* d_in, const int* in_sizes, int n_in,
                              void* d_out, int out_size){
    const float* x  = (const float*)d_in[0];
    const int*   ei = (const int*)  d_in[1];
    const float* W0 = (const float*)d_in[2];
    const float* b0 = (const float*)d_in[3];
    const float* W1 = (const float*)d_in[4];
    const float* b1 = (const float*)d_in[5];
    const float* W2 = (const float*)d_in[6];
    const float* b2 = (const float*)d_in[7];
    const float* Wc = (const float*)d_in[8];
    const float* bc = (const float*)d_in[9];
    float* out = (float*)d_out;

    float *pWp0, *pWp1, *pWp2, *pbp0, *pbp1, *pbp2, *pA, *pB, *pV;
    cudaGetSymbolAddress((void**)&pWp0, g_Wp0);
    cudaGetSymbolAddress((void**)&pWp1, g_Wp1);
    cudaGetSymbolAddress((void**)&pWp2, g_Wp2);
    cudaGetSymbolAddress((void**)&pbp0, g_bp0);
    cudaGetSymbolAddress((void**)&pbp1, g_bp1);
    cudaGetSymbolAddress((void**)&pbp2, g_bp2);
    cudaGetSymbolAddress((void**)&pA,   g_bufA);
    cudaGetSymbolAddress((void**)&pB,   g_bufB);
    cudaGetSymbolAddress((void**)&pV,   g_v);

    // weight padding
    prep_kernel<128,128><<<(128*128 + 255)/256, 256>>>(W0, b0, pWp0, pbp0);
    prep_kernel<256,128><<<(256*128 + 255)/256, 256>>>(W1, b1, pWp1, pbp1);
    prep_kernel<384,256><<<(384*256 + 255)/256, 256>>>(W2, b2, pWp2, pbp2);

    const int RB = (NNODES + 7) / 8;   // 8 warps (rows) per 256-thread block

    lmap0_kernel<<<RB, 256>>>(x);
    scatter_kernel<<<(NEDGES + 7)/8, 256>>>(ei);
    manpre_kernel<<<RB, 256>>>();

    // layer 0: 128 -> 128
    gemm_kernel<128,128><<<dim3(2, (NNODES + 63)/64), 256>>>(pA, pWp0, pbp0, pV);
    rowpost_kernel<128><<<RB, 256>>>(pV, pB);
    // layer 1: 128 -> 256
    gemm_kernel<128,256><<<dim3(4, (NNODES + 63)/64), 256>>>(pB, pWp1, pbp1, pV);
    rowpost_kernel<256><<<RB, 256>>>(pV, pA);
    // layer 2: 256 -> 384
    gemm_kernel<256,384><<<dim3(6, (NNODES + 63)/64), 256>>>(pA, pWp2, pbp2, pV);
    rowpost_kernel<384><<<RB, 256>>>(pV, pB);

    // mean + classifier head
    zero384_kernel<<<1, 384>>>();
    mean_kernel<<<200, 384>>>(pB);
    classify_kernel<<<1, 512>>>(Wc, bc, out);
}

// round 3
// speedup vs baseline: 1.5744x; 1.5744x over previous
#include <cuda_runtime.h>
#include <cstdint>

#define NNODES 50000
#define NEDGES 800000
#define EPSF 1e-7f

// ---------------- static device scratch ----------------
__device__ __align__(16) float g_u0 [NNODES*128];
__device__ __align__(16) float g_acc[NNODES*128];
__device__ __align__(16) float g_v  [NNODES*384];
__device__ __align__(16) float g_bufA[NNODES*384];
__device__ __align__(16) float g_bufB[NNODES*384];
__device__ __align__(16) float g_W0hi[128*128];
__device__ __align__(16) float g_W0lo[128*128];
__device__ __align__(16) float g_W1hi[256*128];
__device__ __align__(16) float g_W1lo[256*128];
__device__ __align__(16) float g_W2hi[384*256];
__device__ __align__(16) float g_W2lo[384*256];
__device__ __align__(16) float g_bp0[128];
__device__ __align__(16) float g_bp1[256];
__device__ __align__(16) float g_bp2[384];
__device__ float g_sums[384];

// ---------------- helpers ----------------
__device__ __forceinline__ float warpSum(float v){
#pragma unroll
    for (int o = 16; o > 0; o >>= 1) v += __shfl_xor_sync(0xffffffffu, v, o);
    return v;
}
__device__ __forceinline__ float arcosh_cl(float x){
    x = fmaxf(x, 1.0f + EPSF);
    return logf(x + sqrtf(x * x - 1.0f));
}
__device__ __forceinline__ uint32_t tf32r(float x){
    uint32_t r; asm("cvt.rna.tf32.f32 %0, %1;" : "=r"(r) : "f"(x)); return r;
}
__device__ __forceinline__ void mma_tf32(float* c, const uint32_t* a, uint32_t b0, uint32_t b1){
    asm volatile(
        "mma.sync.aligned.m16n8k8.row.col.f32.tf32.tf32.f32 "
        "{%0,%1,%2,%3}, {%4,%5,%6,%7}, {%8,%9}, {%0,%1,%2,%3};"
        : "+f"(c[0]), "+f"(c[1]), "+f"(c[2]), "+f"(c[3])
        : "r"(a[0]), "r"(a[1]), "r"(a[2]), "r"(a[3]), "r"(b0), "r"(b1));
}

// ---------------- weight padding + tf32 hi/lo split ----------------
template<int MPAD, int KPAD>
__global__ void prep_kernel(const float* __restrict__ W, const float* __restrict__ b,
                            float* __restrict__ Whi, float* __restrict__ Wlo, float* __restrict__ bp){
    int idx = blockIdx.x * blockDim.x + threadIdx.x;
    if (idx < MPAD * KPAD){
        int m = idx / KPAD, k = idx % KPAD;
        float w = (m >= 1 && k >= 1) ? W[(m - 1) * (KPAD - 1) + (k - 1)] : 0.0f;
        float hi = __uint_as_float(tf32r(w));
        Whi[idx] = hi;
        Wlo[idx] = w - hi;   // rounded to tf32 again inside the GEMM load
    }
    if (idx < MPAD) bp[idx] = (idx >= 1) ? b[idx - 1] : 0.0f;
}

// ---------------- log_map_zero(x) -> u0, acc ----------------
__global__ void lmap0_kernel(const float* __restrict__ x){
    int warp = (blockIdx.x * blockDim.x + threadIdx.x) >> 5;
    if (warp >= NNODES) return;
    int lane = threadIdx.x & 31;
    float4 a = ((const float4*)x)[(size_t)warp * 32 + lane];
    float y0 = __shfl_sync(0xffffffffu, a.x, 0);
    float s = a.x*a.x + a.y*a.y + a.z*a.z + a.w*a.w;
    if (lane == 0) s = a.y*a.y + a.z*a.z + a.w*a.w;
    float S = warpSum(s);
    float dist = arcosh_cl(y0 + EPSF);
    float g = dist / sqrtf(S + EPSF);
    float4 u;
    u.x = (lane == 0) ? 0.0f : g * a.x;
    u.y = g * a.y; u.z = g * a.z; u.w = g * a.w;
    ((float4*)g_u0 )[(size_t)warp * 32 + lane] = u;
    ((float4*)g_acc)[(size_t)warp * 32 + lane] = u;
}

// ---------------- segment_sum via vector red.global ----------------
__global__ void scatter_kernel(const int* __restrict__ ei){
    int warp = (blockIdx.x * blockDim.x + threadIdx.x) >> 5;
    if (warp >= NEDGES) return;
    int lane = threadIdx.x & 31;
    int src = ei[warp];
    int dst = ei[NEDGES + warp];
    float4 v = ((const float4*)g_u0)[(size_t)src * 32 + lane];
    float* addr = g_acc + (size_t)dst * 128 + lane * 4;
    asm volatile("red.global.add.v4.f32 [%0], {%1,%2,%3,%4};"
                 :: "l"(addr), "f"(v.x), "f"(v.y), "f"(v.z), "f"(v.w) : "memory");
}

// ---------------- log_map(exp_map(acc)) -> bufA ----------------
__global__ void manpre_kernel(){
    int warp = (blockIdx.x * blockDim.x + threadIdx.x) >> 5;
    if (warp >= NNODES) return;
    int lane = threadIdx.x & 31;
    float4 a = ((const float4*)g_acc)[(size_t)warp * 32 + lane];
    float s = a.x*a.x + a.y*a.y + a.z*a.z + a.w*a.w;
    float S = warpSum(s);
    float n = sqrtf(fmaxf(S + EPSF, 1e-6f));
    float f = sinhf(fminf(n, 50.0f)) / n;
    float fS = f * f * S;
    float first = sqrtf(1.0f + fS);
    float dist = arcosh_cl(first + EPSF);
    float g = dist / sqrtf(fS + EPSF) * f;
    float4 u; u.x = g*a.x; u.y = g*a.y; u.z = g*a.z; u.w = g*a.w;
    ((float4*)g_bufA)[(size_t)warp * 32 + lane] = u;
}

// ---------------- post-GEMM chain: exp -> log -> relu -> exp -> log ----------------
template<int MP>
__global__ void rowpost_kernel(const float* __restrict__ V, float* __restrict__ U){
    int warp = (blockIdx.x * blockDim.x + threadIdx.x) >> 5;
    if (warp >= NNODES) return;
    int lane = threadIdx.x & 31;
    constexpr int PL = MP / 128;
    const float4* vr = (const float4*)(V + (size_t)warp * MP);
    float4 a[PL];
    float s = 0.0f;
#pragma unroll
    for (int i = 0; i < PL; i++){
        a[i] = vr[i * 32 + lane];
        s += a[i].x*a[i].x + a[i].y*a[i].y + a[i].z*a[i].z + a[i].w*a[i].w;
    }
    float S = warpSum(s);
    float n = sqrtf(fmaxf(S + EPSF, 1e-6f));
    float f = sinhf(fminf(n, 50.0f)) / n;
    float fS = f * f * S;
    float first = sqrtf(1.0f + fS);
    float dist = arcosh_cl(first + EPSF);
    float g1 = dist / sqrtf(fS + EPSF) * f;
    float s2 = 0.0f;
#pragma unroll
    for (int i = 0; i < PL; i++){
        a[i].x = fmaxf(g1 * a[i].x, 0.0f);
        a[i].y = fmaxf(g1 * a[i].y, 0.0f);
        a[i].z = fmaxf(g1 * a[i].z, 0.0f);
        a[i].w = fmaxf(g1 * a[i].w, 0.0f);
        s2 += a[i].x*a[i].x + a[i].y*a[i].y + a[i].z*a[i].z + a[i].w*a[i].w;
    }
    float S2 = warpSum(s2);
    float n2 = sqrtf(fmaxf(S2 + EPSF, 1e-6f));
    float f2 = sinhf(fminf(n2, 50.0f)) / n2;
    float f2S = f2 * f2 * S2;
    float first2 = sqrtf(1.0f + f2S);
    float dist2 = arcosh_cl(first2 + EPSF);
    float g2 = dist2 / sqrtf(f2S + EPSF) * f2;
    float4* ur = (float4*)(U + (size_t)warp * MP);
#pragma unroll
    for (int i = 0; i < PL; i++){
        float4 o; o.x = g2*a[i].x; o.y = g2*a[i].y; o.z = g2*a[i].z; o.w = g2*a[i].w;
        ur[i * 32 + lane] = o;
    }
}

// ---------------- mma.sync tf32 GEMM ----------------
// C[n][m] = A[n][:] . W[m][:] + bias[m], W = Whi + Wlo (tf32 split)
// Block: 256 thr (8 warps, 4m x 2n), tile 128 rows x 128 cols, K-chunks of 32.
#define SASTRIDE 36
static constexpr int MMA_SMEM = 3 * 128 * SASTRIDE * 4;   // 55296 B

template<int K, int MOUT>
__global__ void __launch_bounds__(256, 2) mma_gemm(const float* __restrict__ A,
        const float* __restrict__ Whi, const float* __restrict__ Wlo,
        const float* __restrict__ bias, float* __restrict__ C){
    extern __shared__ float smf[];
    float* sA = smf;
    float* sH = smf + 128 * SASTRIDE;
    float* sL = smf + 2 * 128 * SASTRIDE;
    int tid = threadIdx.x, lane = tid & 31, wid = tid >> 5;
    int brow = blockIdx.y * 128, bcol = blockIdx.x * 128;
    int mw = wid & 3, nw = wid >> 2;
    int gid = lane >> 2, tig = lane & 3;

    float acc[2][8][4];
#pragma unroll
    for (int i = 0; i < 2; i++)
#pragma unroll
        for (int j = 0; j < 8; j++)
#pragma unroll
            for (int l = 0; l < 4; l++) acc[i][j][l] = 0.0f;

    for (int kc = 0; kc < K / 32; kc++){
        int k0g = kc * 32;
#pragma unroll
        for (int i = 0; i < 4; i++){
            int idx = tid + i * 256;
            int r = idx >> 3;
            int c4 = (idx & 7) << 2;
            int gr = brow + r;
            float4 va = (gr < NNODES) ? *(const float4*)(A + (size_t)gr * K + k0g + c4)
                                      : make_float4(0,0,0,0);
            float4 vh = *(const float4*)(Whi + (size_t)(bcol + r) * K + k0g + c4);
            float4 vl = *(const float4*)(Wlo + (size_t)(bcol + r) * K + k0g + c4);
            float* pa = sA + r * SASTRIDE + c4;
            float* ph = sH + r * SASTRIDE + c4;
            float* pl = sL + r * SASTRIDE + c4;
            pa[0]=__uint_as_float(tf32r(va.x)); pa[1]=__uint_as_float(tf32r(va.y));
            pa[2]=__uint_as_float(tf32r(va.z)); pa[3]=__uint_as_float(tf32r(va.w));
            ph[0]=__uint_as_float(tf32r(vh.x)); ph[1]=__uint_as_float(tf32r(vh.y));
            ph[2]=__uint_as_float(tf32r(vh.z)); ph[3]=__uint_as_float(tf32r(vh.w));
            pl[0]=__uint_as_float(tf32r(vl.x)); pl[1]=__uint_as_float(tf32r(vl.y));
            pl[2]=__uint_as_float(tf32r(vl.z)); pl[3]=__uint_as_float(tf32r(vl.w));
        }
        __syncthreads();
#pragma unroll
        for (int ks = 0; ks < 4; ks++){
            int kb = ks * 8;
            uint32_t afr[2][4];
#pragma unroll
            for (int sm2 = 0; sm2 < 2; sm2++){
                int row = mw * 32 + sm2 * 16 + gid;
                afr[sm2][0] = __float_as_uint(sA[row * SASTRIDE + kb + tig]);
                afr[sm2][1] = __float_as_uint(sA[(row + 8) * SASTRIDE + kb + tig]);
                afr[sm2][2] = __float_as_uint(sA[row * SASTRIDE + kb + tig + 4]);
                afr[sm2][3] = __float_as_uint(sA[(row + 8) * SASTRIDE + kb + tig + 4]);
            }
#pragma unroll
            for (int sn = 0; sn < 8; sn++){
                int col = nw * 64 + sn * 8 + gid;
                uint32_t bh0 = __float_as_uint(sH[col * SASTRIDE + kb + tig]);
                uint32_t bh1 = __float_as_uint(sH[col * SASTRIDE + kb + tig + 4]);
                uint32_t bl0 = __float_as_uint(sL[col * SASTRIDE + kb + tig]);
                uint32_t bl1 = __float_as_uint(sL[col * SASTRIDE + kb + tig + 4]);
#pragma unroll
                for (int sm2 = 0; sm2 < 2; sm2++){
                    mma_tf32(acc[sm2][sn], afr[sm2], bh0, bh1);
                    mma_tf32(acc[sm2][sn], afr[sm2], bl0, bl1);
                }
            }
        }
        __syncthreads();
    }
    // epilogue
#pragma unroll
    for (int sm2 = 0; sm2 < 2; sm2++){
#pragma unroll
        for (int sn = 0; sn < 8; sn++){
            int row = brow + mw * 32 + sm2 * 16 + gid;
            int col = bcol + nw * 64 + sn * 8 + tig * 2;
            float2 bb = *(const float2*)(bias + col);
            if (row < NNODES){
                float2 o; o.x = acc[sm2][sn][0] + bb.x; o.y = acc[sm2][sn][1] + bb.y;
                *(float2*)(C + (size_t)row * MOUT + col) = o;
            }
            if (row + 8 < NNODES){
                float2 o; o.x = acc[sm2][sn][2] + bb.x; o.y = acc[sm2][sn][3] + bb.y;
                *(float2*)(C + (size_t)(row + 8) * MOUT + col) = o;
            }
        }
    }
}

// ---------------- mean over nodes ----------------
__global__ void zero384_kernel(){ g_sums[threadIdx.x] = 0.0f; }

__global__ void mean_kernel(const float* __restrict__ U){
    int t = threadIdx.x;
    int start = blockIdx.x * 250;
    int end = start + 250;
    float s = 0.0f;
    for (int nn = start; nn < end; nn++) s += U[(size_t)nn * 384 + t];
    atomicAdd(&g_sums[t], s);
}

// ---------------- final classifier head ----------------
__global__ void classify_kernel(const float* __restrict__ Wc, const float* __restrict__ bc,
                                float* __restrict__ out){
    __shared__ float sh_hm[384];
    __shared__ float sh_warp[16];
    __shared__ float sh_mx[10];
    __shared__ float sh_factor;
    int t = threadIdx.x, lane = t & 31, wid = t >> 5;
    float v = 0.0f;
    if (t < 384) v = g_sums[t] * (1.0f / (float)NNODES);
    if (t == 0) v = 0.0f;
    if (t < 384) sh_hm[t] = v;
    float s = warpSum(v * v);
    if (lane == 0) sh_warp[wid] = s;
    __syncthreads();
    if (t == 0){
        float S = 0.0f;
        for (int i = 0; i < 16; i++) S += sh_warp[i];
        float nrm = sqrtf(S + EPSF);
        float dist = arcosh_cl(0.0f + EPSF);
        sh_factor = dist / nrm;
    }
    __syncthreads();
    float factor = sh_factor;
    if (wid < 9){
        float d = 0.0f;
        for (int j = lane; j < 383; j += 32) d += sh_hm[j + 1] * factor * Wc[wid * 383 + j];
        d = warpSum(d);
        if (lane == 0) sh_mx[wid + 1] = d + bc[wid];
    }
    if (t == 0) sh_mx[0] = 0.0f;
    __syncthreads();
    if (t == 0){
        float mx[10];
#pragma unroll
        for (int i = 0; i < 10; i++) mx[i] = sh_mx[i];
        float S = 0.0f;
        for (int i = 1; i < 10; i++) S += mx[i] * mx[i];
        float n = sqrtf(fmaxf(S + EPSF, 1e-6f));
        float f = sinhf(fminf(n, 50.0f)) / n;
        float fS = f * f * S;
        float hc[10];
        bool cond = (S == 0.0f);
        if (cond){
            for (int i = 0; i < 10; i++) hc[i] = 0.0f;
        } else {
            hc[0] = sqrtf(1.0f + fS);
            for (int i = 1; i < 10; i++) hc[i] = f * mx[i];
        }
        for (int i = 0; i < 10; i++) out[i] = hc[i];
        float x0c = fmaxf(hc[0] + EPSF, 1.0f + EPSF);
        float dd = logf(x0c + sqrtf(x0c * x0c - 1.0f));
        float tn = 0.0f;
        for (int i = 1; i < 10; i++) tn += hc[i] * hc[i];
        float nr = sqrtf(tn + EPSF);
        float gf = dd / nr;
        float lt[10]; lt[0] = 0.0f;
        for (int i = 1; i < 10; i++) lt[i] = gf * hc[i];
        float mmax = lt[0];
        for (int i = 1; i < 10; i++) mmax = fmaxf(mmax, lt[i]);
        float e[10], se = 0.0f;
        for (int i = 0; i < 10; i++){ e[i] = expf(lt[i] - mmax); se += e[i]; }
        float p[10];
        for (int i = 0; i < 10; i++) p[i] = e[i] / se;
        p[0] = 0.0f;
        float S3 = 0.0f;
        for (int i = 1; i < 10; i++) S3 += p[i] * p[i];
        float n3 = sqrtf(fmaxf(S3 + EPSF, 1e-6f));
        float f3 = sinhf(fminf(n3, 50.0f)) / n3;
        float f3S = f3 * f3 * S3;
        out[10] = sqrtf(1.0f + f3S);
        for (int i = 1; i < 10; i++) out[10 + i] = f3 * p[i];
    }
}

// ---------------- launch ----------------
extern "C" void kernel_launch(void* const* d_in, const int* in_sizes, int n_in,
                              void* d_out, int out_size){
    const float* x  = (const float*)d_in[0];
    const int*   ei = (const int*)  d_in[1];
    const float* W0 = (const float*)d_in[2];
    const float* b0 = (const float*)d_in[3];
    const float* W1 = (const float*)d_in[4];
    const float* b1 = (const float*)d_in[5];
    const float* W2 = (const float*)d_in[6];
    const float* b2 = (const float*)d_in[7];
    const float* Wc = (const float*)d_in[8];
    const float* bc = (const float*)d_in[9];
    float* out = (float*)d_out;

    float *pW0h,*pW0l,*pW1h,*pW1l,*pW2h,*pW2l,*pbp0,*pbp1,*pbp2,*pA,*pB,*pV;
    cudaGetSymbolAddress((void**)&pW0h, g_W0hi);
    cudaGetSymbolAddress((void**)&pW0l, g_W0lo);
    cudaGetSymbolAddress((void**)&pW1h, g_W1hi);
    cudaGetSymbolAddress((void**)&pW1l, g_W1lo);
    cudaGetSymbolAddress((void**)&pW2h, g_W2hi);
    cudaGetSymbolAddress((void**)&pW2l, g_W2lo);
    cudaGetSymbolAddress((void**)&pbp0, g_bp0);
    cudaGetSymbolAddress((void**)&pbp1, g_bp1);
    cudaGetSymbolAddress((void**)&pbp2, g_bp2);
    cudaGetSymbolAddress((void**)&pA,   g_bufA);
    cudaGetSymbolAddress((void**)&pB,   g_bufB);
    cudaGetSymbolAddress((void**)&pV,   g_v);

    cudaFuncSetAttribute(mma_gemm<128,128>, cudaFuncAttributeMaxDynamicSharedMemorySize, MMA_SMEM);
    cudaFuncSetAttribute(mma_gemm<128,256>, cudaFuncAttributeMaxDynamicSharedMemorySize, MMA_SMEM);
    cudaFuncSetAttribute(mma_gemm<256,384>, cudaFuncAttributeMaxDynamicSharedMemorySize, MMA_SMEM);

    prep_kernel<128,128><<<(128*128 + 255)/256, 256>>>(W0, b0, pW0h, pW0l, pbp0);
    prep_kernel<256,128><<<(256*128 + 255)/256, 256>>>(W1, b1, pW1h, pW1l, pbp1);
    prep_kernel<384,256><<<(384*256 + 255)/256, 256>>>(W2, b2, pW2h, pW2l, pbp2);

    const int RB = (NNODES + 7) / 8;
    const int NT = (NNODES + 127) / 128;   // 391 row tiles

    lmap0_kernel<<<RB, 256>>>(x);
    scatter_kernel<<<(NEDGES + 7)/8, 256>>>(ei);
    manpre_kernel<<<RB, 256>>>();

    mma_gemm<128,128><<<dim3(1, NT), 256, MMA_SMEM>>>(pA, pW0h, pW0l, pbp0, pV);
    rowpost_kernel<128><<<RB, 256>>>(pV, pB);
    mma_gemm<128,256><<<dim3(2, NT), 256, MMA_SMEM>>>(pB, pW1h, pW1l, pbp1, pV);
    rowpost_kernel<256><<<RB, 256>>>(pV, pA);
    mma_gemm<256,384><<<dim3(3, NT), 256, MMA_SMEM>>>(pA, pW2h, pW2l, pbp2, pV);
    rowpost_kernel<384><<<RB, 256>>>(pV, pB);

    zero384_kernel<<<1, 384>>>();
    mean_kernel<<<200, 384>>>(pB);
    classify_kernel<<<1, 512>>>(Wc, bc, out);
}

// round 5
// speedup vs baseline: 1.6763x; 1.0648x over previous
#include <cuda_runtime.h>
#include <cstdint>

#define NNODES 50000
#define NEDGES 800000
#define EPSF 1e-7f

// ---------------- static device scratch ----------------
__device__ __align__(16) float g_u0 [NNODES*128];
__device__ __align__(16) float g_acc[NNODES*128];
__device__ __align__(16) float g_v  [NNODES*384];
__device__ __align__(16) float g_bufA[NNODES*384];
__device__ __align__(16) float g_bufB[NNODES*384];
__device__ __align__(16) float g_W0hi[128*128];
__device__ __align__(16) float g_W0lo[128*128];
__device__ __align__(16) float g_W1hi[256*128];
__device__ __align__(16) float g_W1lo[256*128];
__device__ __align__(16) float g_W2hi[384*256];
__device__ __align__(16) float g_W2lo[384*256];
__device__ __align__(16) float g_bp0[128];
__device__ __align__(16) float g_bp1[256];
__device__ __align__(16) float g_bp2[384];
__device__ float g_sums[384];

// ---------------- helpers ----------------
__device__ __forceinline__ float warpSum(float v){
#pragma unroll
    for (int o = 16; o > 0; o >>= 1) v += __shfl_xor_sync(0xffffffffu, v, o);
    return v;
}
__device__ __forceinline__ float arcosh_cl(float x){
    x = fmaxf(x, 1.0f + EPSF);
    return logf(x + sqrtf(x * x - 1.0f));
}
__device__ __forceinline__ uint32_t tf32r(float x){
    uint32_t r; asm("cvt.rna.tf32.f32 %0, %1;" : "=r"(r) : "f"(x)); return r;
}
__device__ __forceinline__ float tf32f(float x){ return __uint_as_float(tf32r(x)); }

__device__ __forceinline__ void mma_tf32(float* c, const uint32_t* a, uint32_t b0, uint32_t b1){
    asm volatile(
        "mma.sync.aligned.m16n8k8.row.col.f32.tf32.tf32.f32 "
        "{%0,%1,%2,%3}, {%4,%5,%6,%7}, {%8,%9}, {%0,%1,%2,%3};"
        : "+f"(c[0]), "+f"(c[1]), "+f"(c[2]), "+f"(c[3])
        : "r"(a[0]), "r"(a[1]), "r"(a[2]), "r"(a[3]), "r"(b0), "r"(b1));
}
__device__ __forceinline__ uint32_t smem_u32(const void* p){
    return (uint32_t)__cvta_generic_to_shared(p);
}
__device__ __forceinline__ void cp_async16(uint32_t sdst, const void* gsrc, int srcsize){
    asm volatile("cp.async.cg.shared.global [%0], [%1], 16, %2;"
                 :: "r"(sdst), "l"(gsrc), "r"(srcsize) : "memory");
}
#define CP_COMMIT() asm volatile("cp.async.commit_group;" ::: "memory")
#define CP_WAIT(n)  asm volatile("cp.async.wait_group %0;" :: "n"(n) : "memory")

// ---------------- weight padding + tf32 hi/lo split ----------------
template<int MPAD, int KPAD>
__global__ void prep_kernel(const float* __restrict__ W, const float* __restrict__ b,
                            float* __restrict__ Whi, float* __restrict__ Wlo, float* __restrict__ bp){
    int idx = blockIdx.x * blockDim.x + threadIdx.x;
    if (idx < MPAD * KPAD){
        int m = idx / KPAD, k = idx % KPAD;
        float w = (m >= 1 && k >= 1) ? W[(m - 1) * (KPAD - 1) + (k - 1)] : 0.0f;
        float hi = tf32f(w);
        Whi[idx] = hi;
        Wlo[idx] = tf32f(w - hi);
    }
    if (idx < MPAD) bp[idx] = (idx >= 1) ? b[idx - 1] : 0.0f;
}

// ---------------- log_map_zero(x) -> u0, acc ----------------
__global__ void lmap0_kernel(const float* __restrict__ x){
    int warp = (blockIdx.x * blockDim.x + threadIdx.x) >> 5;
    if (warp >= NNODES) return;
    int lane = threadIdx.x & 31;
    float4 a = ((const float4*)x)[(size_t)warp * 32 + lane];
    float y0 = __shfl_sync(0xffffffffu, a.x, 0);
    float s = a.x*a.x + a.y*a.y + a.z*a.z + a.w*a.w;
    if (lane == 0) s = a.y*a.y + a.z*a.z + a.w*a.w;
    float S = warpSum(s);
    float dist = arcosh_cl(y0 + EPSF);
    float g = dist / sqrtf(S + EPSF);
    float4 u;
    u.x = (lane == 0) ? 0.0f : g * a.x;
    u.y = g * a.y; u.z = g * a.z; u.w = g * a.w;
    ((float4*)g_u0 )[(size_t)warp * 32 + lane] = u;
    ((float4*)g_acc)[(size_t)warp * 32 + lane] = u;
}

// ---------------- segment_sum via vector red.global ----------------
__global__ void scatter_kernel(const int* __restrict__ ei){
    int warp = (blockIdx.x * blockDim.x + threadIdx.x) >> 5;
    if (warp >= NEDGES) return;
    int lane = threadIdx.x & 31;
    int src = ei[warp];
    int dst = ei[NEDGES + warp];
    float4 v = ((const float4*)g_u0)[(size_t)src * 32 + lane];
    float* addr = g_acc + (size_t)dst * 128 + lane * 4;
    asm volatile("red.global.add.v4.f32 [%0], {%1,%2,%3,%4};"
                 :: "l"(addr), "f"(v.x), "f"(v.y), "f"(v.z), "f"(v.w) : "memory");
}

// ---------------- log_map(exp_map(acc)) -> bufA (tf32-rounded) ----------------
__global__ void manpre_kernel(){
    int warp = (blockIdx.x * blockDim.x + threadIdx.x) >> 5;
    if (warp >= NNODES) return;
    int lane = threadIdx.x & 31;
    float4 a = ((const float4*)g_acc)[(size_t)warp * 32 + lane];
    float s = a.x*a.x + a.y*a.y + a.z*a.z + a.w*a.w;
    float S = warpSum(s);
    float n = sqrtf(fmaxf(S + EPSF, 1e-6f));
    float f = sinhf(fminf(n, 50.0f)) / n;
    float fS = f * f * S;
    float first = sqrtf(1.0f + fS);
    float dist = arcosh_cl(first + EPSF);
    float g = dist / sqrtf(fS + EPSF) * f;
    float4 u;
    u.x = tf32f(g*a.x); u.y = tf32f(g*a.y); u.z = tf32f(g*a.z); u.w = tf32f(g*a.w);
    ((float4*)g_bufA)[(size_t)warp * 32 + lane] = u;
}

// ---------------- post-GEMM chain: exp -> log -> relu -> exp -> log (tf32-rounded out) ----------------
template<int MP>
__global__ void rowpost_kernel(const float* __restrict__ V, float* __restrict__ U){
    int warp = (blockIdx.x * blockDim.x + threadIdx.x) >> 5;
    if (warp >= NNODES) return;
    int lane = threadIdx.x & 31;
    constexpr int PL = MP / 128;
    const float4* vr = (const float4*)(V + (size_t)warp * MP);
    float4 a[PL];
    float s = 0.0f;
#pragma unroll
    for (int i = 0; i < PL; i++){
        a[i] = vr[i * 32 + lane];
        s += a[i].x*a[i].x + a[i].y*a[i].y + a[i].z*a[i].z + a[i].w*a[i].w;
    }
    float S = warpSum(s);
    float n = sqrtf(fmaxf(S + EPSF, 1e-6f));
    float f = sinhf(fminf(n, 50.0f)) / n;
    float fS = f * f * S;
    float first = sqrtf(1.0f + fS);
    float dist = arcosh_cl(first + EPSF);
    float g1 = dist / sqrtf(fS + EPSF) * f;
    float s2 = 0.0f;
#pragma unroll
    for (int i = 0; i < PL; i++){
        a[i].x = fmaxf(g1 * a[i].x, 0.0f);
        a[i].y = fmaxf(g1 * a[i].y, 0.0f);
        a[i].z = fmaxf(g1 * a[i].z, 0.0f);
        a[i].w = fmaxf(g1 * a[i].w, 0.0f);
        s2 += a[i].x*a[i].x + a[i].y*a[i].y + a[i].z*a[i].z + a[i].w*a[i].w;
    }
    float S2 = warpSum(s2);
    float n2 = sqrtf(fmaxf(S2 + EPSF, 1e-6f));
    float f2 = sinhf(fminf(n2, 50.0f)) / n2;
    float f2S = f2 * f2 * S2;
    float first2 = sqrtf(1.0f + f2S);
    float dist2 = arcosh_cl(first2 + EPSF);
    float g2 = dist2 / sqrtf(f2S + EPSF) * f2;
    float4* ur = (float4*)(U + (size_t)warp * MP);
#pragma unroll
    for (int i = 0; i < PL; i++){
        float4 o;
        o.x = tf32f(g2*a[i].x); o.y = tf32f(g2*a[i].y);
        o.z = tf32f(g2*a[i].z); o.w = tf32f(g2*a[i].w);
        ur[i * 32 + lane] = o;
    }
}

// ---------------- cp.async double-buffered mma.sync tf32 GEMM ----------------
// C[n][m] = A[n][:] . W[m][:] + bias[m], W = Whi + Wlo (tf32 split, pre-rounded)
// Block: 256 thr (8 warps, 2m x 4n), tile 128 rows x 128 cols, K-chunks of 32.
#define SASTRIDE 36
static constexpr int STG_FLOATS = 3 * 128 * SASTRIDE;           // floats per stage
static constexpr int MMA_SMEM = 2 * STG_FLOATS * 4;             // 110592 B

template<int K, int MOUT>
__global__ void __launch_bounds__(256, 2) mma_gemm(const float* __restrict__ A,
        const float* __restrict__ Whi, const float* __restrict__ Wlo,
        const float* __restrict__ bias, float* __restrict__ C){
    extern __shared__ float smf[];
    int tid = threadIdx.x, lane = tid & 31, wid = tid >> 5;
    int brow = blockIdx.y * 128, bcol = blockIdx.x * 128;
    int mw = wid & 1, nw = wid >> 1;
    int gid = lane >> 2, tig = lane & 3;
    constexpr int NC = K / 32;

    // cp.async copy of one chunk (A,H,L tiles) into stage s
    auto load_stage = [&](int s, int kc){
        float* base = smf + s * STG_FLOATS;
        uint32_t sbA = smem_u32(base);
        uint32_t sbH = smem_u32(base + 128 * SASTRIDE);
        uint32_t sbL = smem_u32(base + 2 * 128 * SASTRIDE);
        int k0 = kc * 32;
#pragma unroll
        for (int i = 0; i < 4; i++){
            int idx = tid + i * 256;
            int r = idx >> 3;
            int c4 = (idx & 7) << 2;
            uint32_t soff = (uint32_t)(r * SASTRIDE + c4) * 4u;
            int gr = brow + r;
            cp_async16(sbA + soff, A + (size_t)gr * K + k0 + c4, (gr < NNODES) ? 16 : 0);
            cp_async16(sbH + soff, Whi + (size_t)(bcol + r) * K + k0 + c4, 16);
            cp_async16(sbL + soff, Wlo + (size_t)(bcol + r) * K + k0 + c4, 16);
        }
        CP_COMMIT();
    };

    float acc[4][4][4];
#pragma unroll
    for (int i = 0; i < 4; i++)
#pragma unroll
        for (int j = 0; j < 4; j++)
#pragma unroll
            for (int l = 0; l < 4; l++) acc[i][j][l] = 0.0f;

    load_stage(0, 0);
    if (NC > 1) load_stage(1, 1);

    for (int kc = 0; kc < NC; kc++){
        int buf = kc & 1;
        if (kc + 1 < NC) { CP_WAIT(1); } else { CP_WAIT(0); }
        __syncthreads();
        const float* sA = smf + buf * STG_FLOATS;
        const float* sH = sA + 128 * SASTRIDE;
        const float* sL = sA + 2 * 128 * SASTRIDE;
#pragma unroll
        for (int ks = 0; ks < 4; ks++){
            int kb = ks * 8;
            uint32_t afr[4][4];
#pragma unroll
            for (int sm2 = 0; sm2 < 4; sm2++){
                int row = mw * 64 + sm2 * 16 + gid;
                afr[sm2][0] = __float_as_uint(sA[row * SASTRIDE + kb + tig]);
                afr[sm2][1] = __float_as_uint(sA[(row + 8) * SASTRIDE + kb + tig]);
                afr[sm2][2] = __float_as_uint(sA[row * SASTRIDE + kb + tig + 4]);
                afr[sm2][3] = __float_as_uint(sA[(row + 8) * SASTRIDE + kb + tig + 4]);
            }
#pragma unroll
            for (int sn = 0; sn < 4; sn++){
                int col = nw * 32 + sn * 8 + gid;
                uint32_t bh0 = __float_as_uint(sH[col * SASTRIDE + kb + tig]);
                uint32_t bh1 = __float_as_uint(sH[col * SASTRIDE + kb + tig + 4]);
                uint32_t bl0 = __float_as_uint(sL[col * SASTRIDE + kb + tig]);
                uint32_t bl1 = __float_as_uint(sL[col * SASTRIDE + kb + tig + 4]);
#pragma unroll
                for (int sm2 = 0; sm2 < 4; sm2++){
                    mma_tf32(acc[sm2][sn], afr[sm2], bh0, bh1);
                    mma_tf32(acc[sm2][sn], afr[sm2], bl0, bl1);
                }
            }
        }
        __syncthreads();
        if (kc + 2 < NC) load_stage(buf, kc + 2);
    }

    // epilogue
#pragma unroll
    for (int sm2 = 0; sm2 < 4; sm2++){
#pragma unroll
        for (int sn = 0; sn < 4; sn++){
            int row = brow + mw * 64 + sm2 * 16 + gid;
            int col = bcol + nw * 32 + sn * 8 + tig * 2;
            float2 bb = *(const float2*)(bias + col);
            if (row < NNODES){
                float2 o; o.x = acc[sm2][sn][0] + bb.x; o.y = acc[sm2][sn][1] + bb.y;
                *(float2*)(C + (size_t)row * MOUT + col) = o;
            }
            if (row + 8 < NNODES){
                float2 o; o.x = acc[sm2][sn][2] + bb.x; o.y = acc[sm2][sn][3] + bb.y;
                *(float2*)(C + (size_t)(row + 8) * MOUT + col) = o;
            }
        }
    }
}

// ---------------- mean over nodes ----------------
__global__ void zero384_kernel(){ g_sums[threadIdx.x] = 0.0f; }

__global__ void mean_kernel(const float* __restrict__ U){
    int t = threadIdx.x;
    int start = blockIdx.x * 250;
    int end = start + 250;
    float s = 0.0f;
    for (int nn = start; nn < end; nn++) s += U[(size_t)nn * 384 + t];
    atomicAdd(&g_sums[t], s);
}

// ---------------- final classifier head ----------------
__global__ void classify_kernel(const float* __restrict__ Wc, const float* __restrict__ bc,
                                float* __restrict__ out){
    __shared__ float sh_hm[384];
    __shared__ float sh_warp[16];
    __shared__ float sh_mx[10];
    __shared__ float sh_factor;
    int t = threadIdx.x, lane = t & 31, wid = t >> 5;
    float v = 0.0f;
    if (t < 384) v = g_sums[t] * (1.0f / (float)NNODES);
    if (t == 0) v = 0.0f;
    if (t < 384) sh_hm[t] = v;
    float s = warpSum(v * v);
    if (lane == 0) sh_warp[wid] = s;
    __syncthreads();
    if (t == 0){
        float S = 0.0f;
        for (int i = 0; i < 16; i++) S += sh_warp[i];
        float nrm = sqrtf(S + EPSF);
        float dist = arcosh_cl(0.0f + EPSF);
        sh_factor = dist / nrm;
    }
    __syncthreads();
    float factor = sh_factor;
    if (wid < 9){
        float d = 0.0f;
        for (int j = lane; j < 383; j += 32) d += sh_hm[j + 1] * factor * Wc[wid * 383 + j];
        d = warpSum(d);
        if (lane == 0) sh_mx[wid + 1] = d + bc[wid];
    }
    if (t == 0) sh_mx[0] = 0.0f;
    __syncthreads();
    if (t == 0){
        float mx[10];
#pragma unroll
        for (int i = 0; i < 10; i++) mx[i] = sh_mx[i];
        float S = 0.0f;
        for (int i = 1; i < 10; i++) S += mx[i] * mx[i];
        float n = sqrtf(fmaxf(S + EPSF, 1e-6f));
        float f = sinhf(fminf(n, 50.0f)) / n;
        float fS = f * f * S;
        float hc[10];
        bool cond = (S == 0.0f);
        if (cond){
            for (int i = 0; i < 10; i++) hc[i] = 0.0f;
        } else {
            hc[0] = sqrtf(1.0f + fS);
            for (int i = 1; i < 10; i++) hc[i] = f * mx[i];
        }
        for (int i = 0; i < 10; i++) out[i] = hc[i];
        float x0c = fmaxf(hc[0] + EPSF, 1.0f + EPSF);
        float dd = logf(x0c + sqrtf(x0c * x0c - 1.0f));
        float tn = 0.0f;
        for (int i = 1; i < 10; i++) tn += hc[i] * hc[i];
        float nr = sqrtf(tn + EPSF);
        float gf = dd / nr;
        float lt[10]; lt[0] = 0.0f;
        for (int i = 1; i < 10; i++) lt[i] = gf * hc[i];
        float mmax = lt[0];
        for (int i = 1; i < 10; i++) mmax = fmaxf(mmax, lt[i]);
        float e[10], se = 0.0f;
        for (int i = 0; i < 10; i++){ e[i] = expf(lt[i] - mmax); se += e[i]; }
        float p[10];
        for (int i = 0; i < 10; i++) p[i] = e[i] / se;
        p[0] = 0.0f;
        float S3 = 0.0f;
        for (int i = 1; i < 10; i++) S3 += p[i] * p[i];
        float n3 = sqrtf(fmaxf(S3 + EPSF, 1e-6f));
        float f3 = sinhf(fminf(n3, 50.0f)) / n3;
        float f3S = f3 * f3 * S3;
        out[10] = sqrtf(1.0f + f3S);
        for (int i = 1; i < 10; i++) out[10 + i] = f3 * p[i];
    }
}

// ---------------- launch ----------------
extern "C" void kernel_launch(void* const* d_in, const int* in_sizes, int n_in,
                              void* d_out, int out_size){
    const float* x  = (const float*)d_in[0];
    const int*   ei = (const int*)  d_in[1];
    const float* W0 = (const float*)d_in[2];
    const float* b0 = (const float*)d_in[3];
    const float* W1 = (const float*)d_in[4];
    const float* b1 = (const float*)d_in[5];
    const float* W2 = (const float*)d_in[6];
    const float* b2 = (const float*)d_in[7];
    const float* Wc = (const float*)d_in[8];
    const float* bc = (const float*)d_in[9];
    float* out = (float*)d_out;

    float *pW0h,*pW0l,*pW1h,*pW1l,*pW2h,*pW2l,*pbp0,*pbp1,*pbp2,*pA,*pB,*pV;
    cudaGetSymbolAddress((void**)&pW0h, g_W0hi);
    cudaGetSymbolAddress((void**)&pW0l, g_W0lo);
    cudaGetSymbolAddress((void**)&pW1h, g_W1hi);
    cudaGetSymbolAddress((void**)&pW1l, g_W1lo);
    cudaGetSymbolAddress((void**)&pW2h, g_W2hi);
    cudaGetSymbolAddress((void**)&pW2l, g_W2lo);
    cudaGetSymbolAddress((void**)&pbp0, g_bp0);
    cudaGetSymbolAddress((void**)&pbp1, g_bp1);
    cudaGetSymbolAddress((void**)&pbp2, g_bp2);
    cudaGetSymbolAddress((void**)&pA,   g_bufA);
    cudaGetSymbolAddress((void**)&pB,   g_bufB);
    cudaGetSymbolAddress((void**)&pV,   g_v);

    cudaFuncSetAttribute(mma_gemm<128,128>, cudaFuncAttributeMaxDynamicSharedMemorySize, MMA_SMEM);
    cudaFuncSetAttribute(mma_gemm<128,256>, cudaFuncAttributeMaxDynamicSharedMemorySize, MMA_SMEM);
    cudaFuncSetAttribute(mma_gemm<256,384>, cudaFuncAttributeMaxDynamicSharedMemorySize, MMA_SMEM);

    prep_kernel<128,128><<<(128*128 + 255)/256, 256>>>(W0, b0, pW0h, pW0l, pbp0);
    prep_kernel<256,128><<<(256*128 + 255)/256, 256>>>(W1, b1, pW1h, pW1l, pbp1);
    prep_kernel<384,256><<<(384*256 + 255)/256, 256>>>(W2, b2, pW2h, pW2l, pbp2);

    const int RB = (NNODES + 7) / 8;
    const int NT = (NNODES + 127) / 128;   // 391 row tiles

    lmap0_kernel<<<RB, 256>>>(x);
    scatter_kernel<<<(NEDGES + 7)/8, 256>>>(ei);
    manpre_kernel<<<RB, 256>>>();

    mma_gemm<128,128><<<dim3(1, NT), 256, MMA_SMEM>>>(pA, pW0h, pW0l, pbp0, pV);
    rowpost_kernel<128><<<RB, 256>>>(pV, pB);
    mma_gemm<128,256><<<dim3(2, NT), 256, MMA_SMEM>>>(pB, pW1h, pW1l, pbp1, pV);
    rowpost_kernel<256><<<RB, 256>>>(pV, pA);
    mma_gemm<256,384><<<dim3(3, NT), 256, MMA_SMEM>>>(pA, pW2h, pW2l, pbp2, pV);
    rowpost_kernel<384><<<RB, 256>>>(pV, pB);

    zero384_kernel<<<1, 384>>>();
    mean_kernel<<<200, 384>>>(pB);
    classify_kernel<<<1, 512>>>(Wc, bc, out);
}